// round 3
// baseline (speedup 1.0000x reference)
#include <cuda_runtime.h>
#include <math.h>

#define NROWS   262144      // 32768 samples * 8 meshes
#define NC      256
#define NTAB    50001
#define VD      36
#define RPC     32          // rows per CTA
#define RPW     4           // rows per warp
#define NTHR    256

typedef unsigned long long u64;

// ---- packed f32x2 helpers (Blackwell FFMA2 path) ----
__device__ __forceinline__ u64 bcast2(float x) {
    u64 r; asm("mov.b64 %0, {%1, %1};" : "=l"(r) : "f"(x)); return r;
}
__device__ __forceinline__ void fma2(u64 &d, u64 a, u64 b) {
    asm("fma.rn.f32x2 %0, %1, %2, %0;" : "+l"(d) : "l"(a), "l"(b));
}
__device__ __forceinline__ float2 unpk(u64 v) {
    float x, y; asm("mov.b64 {%0, %1}, %2;" : "=f"(x), "=f"(y) : "l"(v));
    return make_float2(x, y);
}
__device__ __forceinline__ float fcomp(const float4 &v, int i) {
    return (i == 0) ? v.x : (i == 1) ? v.y : (i == 2) ? v.z : v.w;
}

// Accumulate a K-chunk of a dense layer into packed accumulators.
// Warp layout: 4 rows (r0..r0+3), lane owns cols {lane*4..+3} and {128+lane*4..+3}
// acc[r][0..1] -> cols lane*4 + {0,1},{2,3}; acc[r][2..3] -> cols 128+lane*4 + {0,1},{2,3}
template<int K, int AST>
__device__ __forceinline__ void acc_block(u64 acc[RPW][4],
        const float *act, const float* __restrict__ W,
        int ldw, int colBase, int r0, int lane)
{
    const float* wbase = W + colBase + lane * 4;
#pragma unroll 2
    for (int k = 0; k < K; k += 4) {
        float4 a[RPW];
#pragma unroll
        for (int r = 0; r < RPW; ++r)
            a[r] = *(const float4*)(act + (r0 + r) * AST + k);   // broadcast LDS.128
#pragma unroll
        for (int kk = 0; kk < 4; ++kk) {
            const float* wr = wbase + (size_t)(k + kk) * ldw;
            ulonglong2 w0 = *(const ulonglong2*)(wr);            // cols c..c+3 (coalesced)
            ulonglong2 w1 = *(const ulonglong2*)(wr + 128);      // cols 128+c..+3
#pragma unroll
            for (int r = 0; r < RPW; ++r) {
                u64 av = bcast2(fcomp(a[r], kk));
                fma2(acc[r][0], av, w0.x);
                fma2(acc[r][1], av, w0.y);
                fma2(acc[r][2], av, w1.x);
                fma2(acc[r][3], av, w1.y);
            }
        }
    }
}

__device__ __forceinline__ void zero_acc(u64 acc[RPW][4]) {
#pragma unroll
    for (int r = 0; r < RPW; ++r)
#pragma unroll
        for (int j = 0; j < 4; ++j) acc[r][j] = 0ULL;
}

__device__ __forceinline__ void epilogue(u64 acc[RPW][4], float* out,
        const float* __restrict__ bias, bool relu, int r0, int lane)
{
    float4 b0 = *(const float4*)(bias + lane * 4);
    float4 b1 = *(const float4*)(bias + 128 + lane * 4);
#pragma unroll
    for (int r = 0; r < RPW; ++r) {
        float2 p0 = unpk(acc[r][0]);
        float2 p1 = unpk(acc[r][1]);
        float2 p2 = unpk(acc[r][2]);
        float2 p3 = unpk(acc[r][3]);
        float4 o0 = make_float4(p0.x + b0.x, p0.y + b0.y, p1.x + b0.z, p1.y + b0.w);
        float4 o1 = make_float4(p2.x + b1.x, p2.y + b1.y, p3.x + b1.z, p3.y + b1.w);
        if (relu) {
            o0.x = fmaxf(o0.x, 0.f); o0.y = fmaxf(o0.y, 0.f);
            o0.z = fmaxf(o0.z, 0.f); o0.w = fmaxf(o0.w, 0.f);
            o1.x = fmaxf(o1.x, 0.f); o1.y = fmaxf(o1.y, 0.f);
            o1.z = fmaxf(o1.z, 0.f); o1.w = fmaxf(o1.w, 0.f);
        }
        *(float4*)(out + (r0 + r) * NC + lane * 4) = o0;
        *(float4*)(out + (r0 + r) * NC + 128 + lane * 4) = o1;
    }
}

__global__ void __launch_bounds__(NTHR, 1)
meshcaster_kernel(
    const int*   __restrict__ verts,  const float* __restrict__ barys,
    const float* __restrict__ views,  const float* __restrict__ emb,
    const float* __restrict__ w_proj, const float* __restrict__ b_proj,
    const float* __restrict__ view_W, const float* __restrict__ view_b,
    const float* __restrict__ vert_W, const float* __restrict__ vert_b,
    const float* __restrict__ aW1,    const float* __restrict__ ab1,
    const float* __restrict__ aW2,    const float* __restrict__ ab2,
    const float* __restrict__ cW1,    const float* __restrict__ cb1,
    const float* __restrict__ cW2,    const float* __restrict__ cb2,
    float* __restrict__ out)
{
    extern __shared__ float smem[];
    float* VE = smem;               // [32][256] vertex embeds (kept for color concat)
    float* VV = VE + RPC * NC;      // [32][256] view branch result (kept for color concat)
    float* B0 = VV + RPC * NC;      // [32][256] work
    float* B1 = B0 + RPC * NC;      // [32][256] work
    float* EM = B1 + RPC * NC;      // [32][36]  sincos embedding

    const int tid = threadIdx.x, warp = tid >> 5, lane = tid & 31;
    const int r0 = warp * RPW;
    const int base = blockIdx.x * RPC;

    // ---- Phase 1: gather + max_norm(1.0) renorm + barycentric blend -> VE ----
    for (int rr = 0; rr < RPW; ++rr) {
        int r = r0 + rr, row = base + r, mesh = row & 7;
        float4 acc0 = make_float4(0.f, 0.f, 0.f, 0.f);
        float4 acc1 = make_float4(0.f, 0.f, 0.f, 0.f);
#pragma unroll
        for (int v = 0; v < 3; ++v) {
            int idx = verts[row * 3 + v] + 1;
            const float* ep = emb + ((size_t)mesh * NTAB + (size_t)idx) * NC;
            float4 e0 = *(const float4*)(ep + lane * 4);
            float4 e1 = *(const float4*)(ep + 128 + lane * 4);
            float ss = e0.x*e0.x + e0.y*e0.y + e0.z*e0.z + e0.w*e0.w
                     + e1.x*e1.x + e1.y*e1.y + e1.z*e1.z + e1.w*e1.w;
#pragma unroll
            for (int o = 16; o > 0; o >>= 1) ss += __shfl_xor_sync(0xffffffffu, ss, o);
            float nrm = sqrtf(ss);
            float sc = barys[row * 3 + v];
            if (nrm > 1.f) sc *= 1.f / fmaxf(nrm, 1e-7f);
            acc0.x += sc * e0.x; acc0.y += sc * e0.y; acc0.z += sc * e0.z; acc0.w += sc * e0.w;
            acc1.x += sc * e1.x; acc1.y += sc * e1.y; acc1.z += sc * e1.z; acc1.w += sc * e1.w;
        }
        *(float4*)(VE + r * NC + lane * 4) = acc0;
        *(float4*)(VE + r * NC + 128 + lane * 4) = acc1;
    }

    // ---- Phase 2: sincos embedding (order: [l][sin|cos][xyz]) -> EM ----
    for (int t = lane; t < RPW * VD; t += 32) {
        int rr = t / VD, j = t % VD;
        int l = j / 6, rem = j % 6, s = rem / 3, d = rem % 3;
        float x = views[(base + r0 + rr) * 3 + d];
        float fx = (float)(1 << l) * x;
        EM[(r0 + rr) * VD + j] = s ? cosf(fx) : sinf(fx);
    }
    __syncwarp();

    u64 acc[RPW][4];

    // ---- view branch: proj (no act), then 2x Linear+ReLU ----
    zero_acc(acc);
    acc_block<VD, VD>(acc, EM, w_proj, NC, 0, r0, lane);
    epilogue(acc, B0, b_proj, false, r0, lane);
    __syncwarp();
    zero_acc(acc);
    acc_block<NC, NC>(acc, B0, view_W, NC, 0, r0, lane);
    epilogue(acc, B1, view_b, true, r0, lane);
    __syncwarp();
    zero_acc(acc);
    acc_block<NC, NC>(acc, B1, view_W + NC * NC, NC, 0, r0, lane);
    epilogue(acc, VV, view_b + NC, true, r0, lane);
    __syncwarp();

    // ---- alpha branch: 2x Linear+ReLU on VE, then Linear (no act) ----
    zero_acc(acc);
    acc_block<NC, NC>(acc, VE, vert_W, NC, 0, r0, lane);
    epilogue(acc, B0, vert_b, true, r0, lane);
    __syncwarp();
    zero_acc(acc);
    acc_block<NC, NC>(acc, B0, vert_W + NC * NC, NC, 0, r0, lane);
    epilogue(acc, B1, vert_b + NC, true, r0, lane);
    __syncwarp();
    zero_acc(acc);
    acc_block<NC, NC>(acc, B1, aW1, NC, 0, r0, lane);
    epilogue(acc, B0, ab1, false, r0, lane);
    __syncwarp();

    // ---- alpha head: t @ alpha_W2 + b2 (scalar per row) ----
    float ab2v = ab2[0];
    float alphas[RPW];
    for (int rr = 0; rr < RPW; ++rr) {
        const float* t = B0 + (r0 + rr) * NC;
        float s = 0.f;
#pragma unroll
        for (int g = 0; g < 2; ++g) {
            int off = g * 128 + lane * 4;
#pragma unroll
            for (int j = 0; j < 4; ++j) s += t[off + j] * aW2[off + j];
        }
#pragma unroll
        for (int o = 16; o > 0; o >>= 1) s += __shfl_xor_sync(0xffffffffu, s, o);
        alphas[rr] = s + ab2v;
    }
    __syncwarp();

    // ---- color layer 1: [VV | VE] (512) @ cW1 (512x512) + cb1, no act ----
    // output cols 0..255 -> B0
    zero_acc(acc);
    acc_block<NC, NC>(acc, VV, cW1, 512, 0, r0, lane);
    acc_block<NC, NC>(acc, VE, cW1 + 256 * 512, 512, 0, r0, lane);
    epilogue(acc, B0, cb1, false, r0, lane);
    // output cols 256..511 -> B1
    zero_acc(acc);
    acc_block<NC, NC>(acc, VV, cW1, 512, 256, r0, lane);
    acc_block<NC, NC>(acc, VE, cW1 + 256 * 512, 512, 256, r0, lane);
    epilogue(acc, B1, cb1 + 256, false, r0, lane);
    __syncwarp();

    // ---- color head: u (512) @ cW2 (512x3) + cb2, write [rgb, alpha] ----
    for (int rr = 0; rr < RPW; ++rr) {
        int row = base + r0 + rr;
        const float* u0 = B0 + (r0 + rr) * NC;   // k 0..255
        const float* u1 = B1 + (r0 + rr) * NC;   // k 256..511
        float s0 = 0.f, s1 = 0.f, s2 = 0.f;
#pragma unroll
        for (int g = 0; g < 2; ++g) {
            int off = g * 128 + lane * 4;
#pragma unroll
            for (int j = 0; j < 4; ++j) {
                float uv = u0[off + j];
                const float* w = cW2 + (size_t)(off + j) * 3;
                s0 += uv * w[0]; s1 += uv * w[1]; s2 += uv * w[2];
                uv = u1[off + j];
                w = cW2 + (size_t)(256 + off + j) * 3;
                s0 += uv * w[0]; s1 += uv * w[1]; s2 += uv * w[2];
            }
        }
#pragma unroll
        for (int o = 16; o > 0; o >>= 1) {
            s0 += __shfl_xor_sync(0xffffffffu, s0, o);
            s1 += __shfl_xor_sync(0xffffffffu, s1, o);
            s2 += __shfl_xor_sync(0xffffffffu, s2, o);
        }
        if (lane == 0) {
            float4 ov = make_float4(s0 + cb2[0], s1 + cb2[1], s2 + cb2[2], alphas[rr]);
            *(float4*)(out + (size_t)row * 4) = ov;
        }
    }
}

extern "C" void kernel_launch(void* const* d_in, const int* in_sizes, int n_in,
                              void* d_out, int out_size)
{
    const int*   verts  = (const int*)  d_in[0];
    const float* barys  = (const float*)d_in[1];
    const float* views  = (const float*)d_in[2];
    const float* emb    = (const float*)d_in[3];
    const float* w_proj = (const float*)d_in[4];
    const float* b_proj = (const float*)d_in[5];
    const float* view_W = (const float*)d_in[6];
    const float* view_b = (const float*)d_in[7];
    const float* vert_W = (const float*)d_in[8];
    const float* vert_b = (const float*)d_in[9];
    const float* aW1    = (const float*)d_in[10];
    const float* ab1    = (const float*)d_in[11];
    const float* aW2    = (const float*)d_in[12];
    const float* ab2    = (const float*)d_in[13];
    const float* cW1    = (const float*)d_in[14];
    const float* cb1    = (const float*)d_in[15];
    const float* cW2    = (const float*)d_in[16];
    const float* cb2    = (const float*)d_in[17];
    float* out = (float*)d_out;

    size_t smem = (size_t)(4 * RPC * NC + RPC * VD) * sizeof(float);  // 135,680 B
    cudaFuncSetAttribute(meshcaster_kernel,
                         cudaFuncAttributeMaxDynamicSharedMemorySize, (int)smem);
    meshcaster_kernel<<<NROWS / RPC, NTHR, smem>>>(
        verts, barys, views, emb, w_proj, b_proj, view_W, view_b,
        vert_W, vert_b, aW1, ab1, aW2, ab2, cW1, cb1, cW2, cb2, out);
}

// round 4
// speedup vs baseline: 2.5868x; 2.5868x over previous
#include <cuda_runtime.h>
#include <math.h>

#define NROWS   262144
#define NC      256
#define NTAB    50001
#define VD      36
#define RPC     16          // rows per CTA
#define RPW     4           // rows per warp
#define NTHR    128

typedef unsigned long long u64;

// collapsed head weights
__device__ float g_cW[512 * 3];   // cW1 @ cW2
__device__ float g_cb[3];         // cb1 @ cW2 + cb2
__device__ float g_aW[256];       // aW1 @ aW2
__device__ float g_ab;            // ab1 @ aW2 + ab2

__global__ void prep_kernel(const float* __restrict__ cW1, const float* __restrict__ cb1,
                            const float* __restrict__ cW2, const float* __restrict__ cb2,
                            const float* __restrict__ aW1, const float* __restrict__ ab1,
                            const float* __restrict__ aW2, const float* __restrict__ ab2)
{
    int t = blockIdx.x * blockDim.x + threadIdx.x;
    if (t < 512 * 3) {
        int k = t / 3, j = t % 3;
        float s = 0.f;
        for (int m = 0; m < 512; ++m) s += cW1[k * 512 + m] * cW2[m * 3 + j];
        g_cW[t] = s;
    } else if (t < 512 * 3 + 3) {
        int j = t - 512 * 3;
        float s = cb2[j];
        for (int m = 0; m < 512; ++m) s += cb1[m] * cW2[m * 3 + j];
        g_cb[j] = s;
    } else if (t == 512 * 3 + 3) {
        float s = ab2[0];
        for (int m = 0; m < 256; ++m) s += ab1[m] * aW2[m];
        g_ab = s;
    } else if (t >= 2048 - 256) {             // last 256 threads do g_aW
        int k = t - (2048 - 256);
        float s = 0.f;
        for (int m = 0; m < 256; ++m) s += aW1[k * 256 + m] * aW2[m];
        g_aW[k] = s;
    }
}

// ---- packed f32x2 helpers ----
__device__ __forceinline__ u64 bcast2(float x) {
    u64 r; asm("mov.b64 %0, {%1, %1};" : "=l"(r) : "f"(x)); return r;
}
__device__ __forceinline__ void fma2(u64 &d, u64 a, u64 b) {
    asm("fma.rn.f32x2 %0, %1, %2, %0;" : "+l"(d) : "l"(a), "l"(b));
}
__device__ __forceinline__ float2 unpk(u64 v) {
    float x, y; asm("mov.b64 {%0, %1}, %2;" : "=f"(x), "=f"(y) : "l"(v));
    return make_float2(x, y);
}
__device__ __forceinline__ float fcomp(const float4 &v, int i) {
    return (i == 0) ? v.x : (i == 1) ? v.y : (i == 2) ? v.z : v.w;
}

template<int K, int AST>
__device__ __forceinline__ void acc_block(u64 acc[RPW][4],
        const float *act, const float* __restrict__ W,
        int ldw, int r0, int lane)
{
    const float* wbase = W + lane * 4;
#pragma unroll 2
    for (int k = 0; k < K; k += 4) {
        float4 a[RPW];
#pragma unroll
        for (int r = 0; r < RPW; ++r)
            a[r] = *(const float4*)(act + (r0 + r) * AST + k);
#pragma unroll
        for (int kk = 0; kk < 4; ++kk) {
            const float* wr = wbase + (size_t)(k + kk) * ldw;
            ulonglong2 w0 = *(const ulonglong2*)(wr);
            ulonglong2 w1 = *(const ulonglong2*)(wr + 128);
#pragma unroll
            for (int r = 0; r < RPW; ++r) {
                u64 av = bcast2(fcomp(a[r], kk));
                fma2(acc[r][0], av, w0.x);
                fma2(acc[r][1], av, w0.y);
                fma2(acc[r][2], av, w1.x);
                fma2(acc[r][3], av, w1.y);
            }
        }
    }
}

__device__ __forceinline__ void zero_acc(u64 acc[RPW][4]) {
#pragma unroll
    for (int r = 0; r < RPW; ++r)
#pragma unroll
        for (int j = 0; j < 4; ++j) acc[r][j] = 0ULL;
}

__device__ __forceinline__ void epilogue(u64 acc[RPW][4], float* out,
        const float* __restrict__ bias, bool relu, int r0, int lane)
{
    float4 b0 = *(const float4*)(bias + lane * 4);
    float4 b1 = *(const float4*)(bias + 128 + lane * 4);
#pragma unroll
    for (int r = 0; r < RPW; ++r) {
        float2 p0 = unpk(acc[r][0]);
        float2 p1 = unpk(acc[r][1]);
        float2 p2 = unpk(acc[r][2]);
        float2 p3 = unpk(acc[r][3]);
        float4 o0 = make_float4(p0.x + b0.x, p0.y + b0.y, p1.x + b0.z, p1.y + b0.w);
        float4 o1 = make_float4(p2.x + b1.x, p2.y + b1.y, p3.x + b1.z, p3.y + b1.w);
        if (relu) {
            o0.x = fmaxf(o0.x, 0.f); o0.y = fmaxf(o0.y, 0.f);
            o0.z = fmaxf(o0.z, 0.f); o0.w = fmaxf(o0.w, 0.f);
            o1.x = fmaxf(o1.x, 0.f); o1.y = fmaxf(o1.y, 0.f);
            o1.z = fmaxf(o1.z, 0.f); o1.w = fmaxf(o1.w, 0.f);
        }
        *(float4*)(out + (r0 + r) * NC + lane * 4) = o0;
        *(float4*)(out + (r0 + r) * NC + 128 + lane * 4) = o1;
    }
}

__global__ void __launch_bounds__(NTHR, 3)
meshcaster_kernel(
    const int*   __restrict__ verts,  const float* __restrict__ barys,
    const float* __restrict__ views,  const float* __restrict__ emb,
    const float* __restrict__ w_proj, const float* __restrict__ b_proj,
    const float* __restrict__ view_W, const float* __restrict__ view_b,
    const float* __restrict__ vert_W, const float* __restrict__ vert_b,
    float* __restrict__ out)
{
    extern __shared__ float smem[];
    float* VE = smem;               // [16][256] vertex embeds (kept for color head)
    float* VV = VE + RPC * NC;      // [16][256] view result (kept for color head)
    float* B0 = VV + RPC * NC;      // [16][256] work
    float* B1 = B0 + RPC * NC;      // [16][256] work
    float* EM = B1 + RPC * NC;      // [16][36]  sincos embedding

    const int tid = threadIdx.x, warp = tid >> 5, lane = tid & 31;
    const int r0 = warp * RPW;
    const int base = blockIdx.x * RPC;

    // ---- gather + max_norm renorm + barycentric blend -> VE ----
    for (int rr = 0; rr < RPW; ++rr) {
        int r = r0 + rr, row = base + r, mesh = row & 7;
        float4 acc0 = make_float4(0.f, 0.f, 0.f, 0.f);
        float4 acc1 = make_float4(0.f, 0.f, 0.f, 0.f);
#pragma unroll
        for (int v = 0; v < 3; ++v) {
            int idx = verts[row * 3 + v] + 1;
            const float* ep = emb + ((size_t)mesh * NTAB + (size_t)idx) * NC;
            float4 e0 = *(const float4*)(ep + lane * 4);
            float4 e1 = *(const float4*)(ep + 128 + lane * 4);
            float ss = e0.x*e0.x + e0.y*e0.y + e0.z*e0.z + e0.w*e0.w
                     + e1.x*e1.x + e1.y*e1.y + e1.z*e1.z + e1.w*e1.w;
#pragma unroll
            for (int o = 16; o > 0; o >>= 1) ss += __shfl_xor_sync(0xffffffffu, ss, o);
            float nrm = sqrtf(ss);
            float sc = barys[row * 3 + v];
            if (nrm > 1.f) sc *= 1.f / fmaxf(nrm, 1e-7f);
            acc0.x += sc * e0.x; acc0.y += sc * e0.y; acc0.z += sc * e0.z; acc0.w += sc * e0.w;
            acc1.x += sc * e1.x; acc1.y += sc * e1.y; acc1.z += sc * e1.z; acc1.w += sc * e1.w;
        }
        *(float4*)(VE + r * NC + lane * 4) = acc0;
        *(float4*)(VE + r * NC + 128 + lane * 4) = acc1;
    }

    // ---- sincos embedding ----
    for (int t = lane; t < RPW * VD; t += 32) {
        int rr = t / VD, j = t % VD;
        int l = j / 6, rem = j % 6, s = rem / 3, d = rem % 3;
        float x = views[(base + r0 + rr) * 3 + d];
        float fx = (float)(1 << l) * x;
        EM[(r0 + rr) * VD + j] = s ? cosf(fx) : sinf(fx);
    }
    __syncwarp();

    u64 acc[RPW][4];

    // ---- view branch ----
    zero_acc(acc);
    acc_block<VD, VD>(acc, EM, w_proj, NC, r0, lane);
    epilogue(acc, B0, b_proj, false, r0, lane);
    __syncwarp();
    zero_acc(acc);
    acc_block<NC, NC>(acc, B0, view_W, NC, r0, lane);
    epilogue(acc, B1, view_b, true, r0, lane);
    __syncwarp();
    zero_acc(acc);
    acc_block<NC, NC>(acc, B1, view_W + NC * NC, NC, r0, lane);
    epilogue(acc, VV, view_b + NC, true, r0, lane);
    __syncwarp();

    // ---- alpha trunk: 2x Linear+ReLU on VE ----
    zero_acc(acc);
    acc_block<NC, NC>(acc, VE, vert_W, NC, r0, lane);
    epilogue(acc, B0, vert_b, true, r0, lane);
    __syncwarp();
    zero_acc(acc);
    acc_block<NC, NC>(acc, B0, vert_W + NC * NC, NC, r0, lane);
    epilogue(acc, B1, vert_b + NC, true, r0, lane);
    __syncwarp();

    // ---- collapsed alpha head: B1 @ g_aW + g_ab ----
    float ab2v = g_ab;
    float alphas[RPW];
    for (int rr = 0; rr < RPW; ++rr) {
        const float* t = B1 + (r0 + rr) * NC;
        float s = 0.f;
#pragma unroll
        for (int g = 0; g < 2; ++g) {
            int off = g * 128 + lane * 4;
#pragma unroll
            for (int j = 0; j < 4; ++j) s += t[off + j] * g_aW[off + j];
        }
#pragma unroll
        for (int o = 16; o > 0; o >>= 1) s += __shfl_xor_sync(0xffffffffu, s, o);
        alphas[rr] = s + ab2v;
    }

    // ---- collapsed color head: [VV | VE] (512) @ g_cW (512x3) + g_cb ----
    for (int rr = 0; rr < RPW; ++rr) {
        int row = base + r0 + rr;
        const float* v0 = VV + (r0 + rr) * NC;   // k 0..255
        const float* v1 = VE + (r0 + rr) * NC;   // k 256..511
        float s0 = 0.f, s1 = 0.f, s2 = 0.f;
#pragma unroll
        for (int g = 0; g < 2; ++g) {
            int off = g * 128 + lane * 4;
#pragma unroll
            for (int j = 0; j < 4; ++j) {
                float uv = v0[off + j];
                const float* w = g_cW + (size_t)(off + j) * 3;
                s0 += uv * w[0]; s1 += uv * w[1]; s2 += uv * w[2];
                uv = v1[off + j];
                w = g_cW + (size_t)(256 + off + j) * 3;
                s0 += uv * w[0]; s1 += uv * w[1]; s2 += uv * w[2];
            }
        }
#pragma unroll
        for (int o = 16; o > 0; o >>= 1) {
            s0 += __shfl_xor_sync(0xffffffffu, s0, o);
            s1 += __shfl_xor_sync(0xffffffffu, s1, o);
            s2 += __shfl_xor_sync(0xffffffffu, s2, o);
        }
        if (lane == 0) {
            float4 ov = make_float4(s0 + g_cb[0], s1 + g_cb[1], s2 + g_cb[2], alphas[rr]);
            *(float4*)(out + (size_t)row * 4) = ov;
        }
    }
}

extern "C" void kernel_launch(void* const* d_in, const int* in_sizes, int n_in,
                              void* d_out, int out_size)
{
    const int*   verts  = (const int*)  d_in[0];
    const float* barys  = (const float*)d_in[1];
    const float* views  = (const float*)d_in[2];
    const float* emb    = (const float*)d_in[3];
    const float* w_proj = (const float*)d_in[4];
    const float* b_proj = (const float*)d_in[5];
    const float* view_W = (const float*)d_in[6];
    const float* view_b = (const float*)d_in[7];
    const float* vert_W = (const float*)d_in[8];
    const float* vert_b = (const float*)d_in[9];
    const float* aW1    = (const float*)d_in[10];
    const float* ab1    = (const float*)d_in[11];
    const float* aW2    = (const float*)d_in[12];
    const float* ab2    = (const float*)d_in[13];
    const float* cW1    = (const float*)d_in[14];
    const float* cb1    = (const float*)d_in[15];
    const float* cW2    = (const float*)d_in[16];
    const float* cb2    = (const float*)d_in[17];
    float* out = (float*)d_out;

    prep_kernel<<<8, 256>>>(cW1, cb1, cW2, cb2, aW1, ab1, aW2, ab2);

    size_t smem = (size_t)(4 * RPC * NC + RPC * VD) * sizeof(float);  // 67,840 B
    cudaFuncSetAttribute(meshcaster_kernel,
                         cudaFuncAttributeMaxDynamicSharedMemorySize, (int)smem);
    meshcaster_kernel<<<NROWS / RPC, NTHR, smem>>>(
        verts, barys, views, emb, w_proj, b_proj, view_W, view_b,
        vert_W, vert_b, out);
}

// round 6
// speedup vs baseline: 4.0038x; 1.5478x over previous
#include <cuda_runtime.h>
#include <cuda_bf16.h>
#include <math.h>
#include <stdint.h>

#define NROWS 262144
#define NTAB  50001
#define NC    256

// SMEM byte offsets from dynamic base
#define OFF_AHI  0            // 128 x 264 bf16 = 67584
#define OFF_ALO  67584
#define OFF_WBUF 135168       // 73728: Whi @+0 (256x72 bf16), Wlo @+36864
#define OFF_BIAS 208896       // 1280 floats
#define OFF_CW   214016       // 1536 floats
#define OFF_AW   220160       // 256 floats
#define OFF_CROW 221184       // 128 x 4 floats
#define OFF_SCL  223232       // 384 floats
#define SM_REQ   224768
#define ASTR 264
#define WSTR 72

__device__ __align__(16) __nv_bfloat16 g_wT[4][2][65536]; // [vert0,vert1,view0,view1][hi,lo][n*256+k]
__device__ __align__(16) __nv_bfloat16 g_wP[2][16384];    // proj [hi,lo][n*64+k]
__device__ float g_cWd[1536], g_aWd[256], g_cbd[3], g_abd;

// ---------------- low-level helpers ----------------
__device__ __forceinline__ uint32_t smem_u32(const void* p) {
    uint32_t a;
    asm("{ .reg .u64 t; cvta.to.shared.u64 t, %1; cvt.u32.u64 %0, t; }" : "=r"(a) : "l"(p));
    return a;
}
__device__ __forceinline__ void ldsm4(uint32_t r[4], uint32_t a) {
    asm volatile("ldmatrix.sync.aligned.m8n8.x4.shared.b16 {%0,%1,%2,%3}, [%4];"
        : "=r"(r[0]), "=r"(r[1]), "=r"(r[2]), "=r"(r[3]) : "r"(a));
}
__device__ __forceinline__ void mma16816(float c[4], const uint32_t a[4], uint32_t b0, uint32_t b1) {
    asm volatile("mma.sync.aligned.m16n8k16.row.col.f32.bf16.bf16.f32 "
        "{%0,%1,%2,%3},{%4,%5,%6,%7},{%8,%9},{%0,%1,%2,%3};"
        : "+f"(c[0]), "+f"(c[1]), "+f"(c[2]), "+f"(c[3])
        : "r"(a[0]), "r"(a[1]), "r"(a[2]), "r"(a[3]), "r"(b0), "r"(b1));
}
__device__ __forceinline__ void cp16(uint32_t d, const void* s) {
    asm volatile("cp.async.cg.shared.global [%0], [%1], 16;" :: "r"(d), "l"(s));
}
__device__ __forceinline__ void split2(float f0, float f1, uint32_t &h, uint32_t &l) {
    __nv_bfloat162 hh = __floats2bfloat162_rn(f0, f1);
    float r0 = f0 - __bfloat162float(hh.x);
    float r1 = f1 - __bfloat162float(hh.y);
    __nv_bfloat162 ll = __floats2bfloat162_rn(r0, r1);
    h = *(uint32_t*)&hh; l = *(uint32_t*)&ll;
}

// ---------------- prep kernel ----------------
__global__ void prep_kernel(const float* __restrict__ w_proj, const float* __restrict__ view_W,
                            const float* __restrict__ vert_W,
                            const float* __restrict__ aW1, const float* __restrict__ ab1,
                            const float* __restrict__ aW2, const float* __restrict__ ab2,
                            const float* __restrict__ cW1, const float* __restrict__ cb1,
                            const float* __restrict__ cW2, const float* __restrict__ cb2)
{
    int t = blockIdx.x * blockDim.x + threadIdx.x;
    if (t < 262144) {
        int layer = t >> 16, e = t & 65535, n = e >> 8, k = e & 255;
        const float* W = (layer < 2) ? (vert_W + layer * 65536) : (view_W + (layer - 2) * 65536);
        float w = W[k * 256 + n];
        __nv_bfloat16 hb = __float2bfloat16(w);
        g_wT[layer][0][n * 256 + k] = hb;
        g_wT[layer][1][n * 256 + k] = __float2bfloat16(w - __bfloat162float(hb));
    } else if (t < 262144 + 16384) {
        int e = t - 262144, n = e >> 6, k = e & 63;
        float w = (k < 36) ? w_proj[k * 256 + n] : 0.f;
        __nv_bfloat16 hb = __float2bfloat16(w);
        g_wP[0][n * 64 + k] = hb;
        g_wP[1][n * 64 + k] = __float2bfloat16(w - __bfloat162float(hb));
    } else if (t < 262144 + 16384 + 1536) {
        int e = t - 262144 - 16384, kk = e / 3, j = e - kk * 3;
        float s = 0.f;
        for (int m = 0; m < 512; ++m) s += cW1[kk * 512 + m] * cW2[m * 3 + j];
        g_cWd[e] = s;
    } else if (t < 262144 + 16384 + 1536 + 3) {
        int j = t - 262144 - 16384 - 1536;
        float s = cb2[j];
        for (int m = 0; m < 512; ++m) s += cb1[m] * cW2[m * 3 + j];
        g_cbd[j] = s;
    } else if (t < 262144 + 16384 + 1536 + 3 + 256) {
        int kk = t - 262144 - 16384 - 1536 - 3;
        float s = 0.f;
        for (int m = 0; m < 256; ++m) s += aW1[kk * 256 + m] * aW2[m];
        g_aWd[kk] = s;
    } else if (t == 262144 + 16384 + 1536 + 3 + 256) {
        float s = ab2[0];
        for (int m = 0; m < 256; ++m) s += ab1[m] * aW2[m];
        g_abd = s;
    }
}

// ---------------- fused layer: GEMM(128x256xK) + epilogue ----------------
// MODE 0: store relu; 1: store no-relu; 2: alpha head (relu); 3: color head (relu)
template<int KFULL, int MODE>
__device__ void do_layer(char* sm, uint32_t smb,
    const __nv_bfloat16* __restrict__ WgHi, const __nv_bfloat16* __restrict__ WgLo,
    const float* __restrict__ bias)
{
    const int tid = threadIdx.x, lane = tid & 31, w = tid >> 5;
    const int mwarp = w >> 1, nwarp = w & 1;
    const int rowin = lane & 7, tsel = lane >> 3;

    float acc[2][16][4];
#pragma unroll
    for (int mt = 0; mt < 2; ++mt)
#pragma unroll
        for (int nt = 0; nt < 16; ++nt)
#pragma unroll
            for (int j = 0; j < 4; ++j) acc[mt][nt][j] = 0.f;

    uint32_t aoffH[2], aoffL[2];
#pragma unroll
    for (int mt = 0; mt < 2; ++mt) {
        int row = mwarp * 32 + mt * 16 + rowin + (tsel & 1) * 8;
        int ks = (tsel >> 1) * 8;
        aoffH[mt] = smb + OFF_AHI + (uint32_t)(row * ASTR + ks) * 2;
        aoffL[mt] = smb + OFF_ALO + (uint32_t)(row * ASTR + ks) * 2;
    }
    const int rowB = rowin + (tsel >> 1) * 8;
    const int ksB  = (tsel & 1) * 8;
    uint32_t boff[8];
#pragma unroll
    for (int g = 0; g < 8; ++g) {
        int nb = nwarp * 64 + ((g < 4) ? g * 16 : 128 + (g - 4) * 16);
        boff[g] = smb + OFF_WBUF + (uint32_t)((nb + rowB) * WSTR + ksB) * 2;
    }

    const int nch = KFULL / 64;
    for (int c = 0; c < nch; ++c) {
        // copy chunk (Whi, Wlo: 256 n-rows x 64 k) into SMEM
#pragma unroll
        for (int q = 0; q < 16; ++q) {
            int idx = q * 256 + tid;
            int mat = idx >> 11, rem = idx & 2047, r = rem >> 3, s = rem & 7;
            const __nv_bfloat16* src = (mat ? WgLo : WgHi) + r * KFULL + c * 64 + s * 8;
            uint32_t dst = smb + OFF_WBUF + mat * 36864 + (uint32_t)(r * 144 + s * 16);
            cp16(dst, src);
        }
        asm volatile("cp.async.commit_group;");
        asm volatile("cp.async.wait_group 0;" ::: "memory");
        __syncthreads();
#pragma unroll
        for (int kk = 0; kk < 4; ++kk) {
            int kg2 = (c * 64 + kk * 16) * 2;
            int kl2 = (kk * 16) * 2;
            uint32_t ah[2][4], al[2][4];
            ldsm4(ah[0], aoffH[0] + kg2); ldsm4(ah[1], aoffH[1] + kg2);
            ldsm4(al[0], aoffL[0] + kg2); ldsm4(al[1], aoffL[1] + kg2);
#pragma unroll
            for (int g = 0; g < 8; ++g) {
                uint32_t wh[4], wl[4];
                ldsm4(wh, boff[g] + kl2);
                ldsm4(wl, boff[g] + kl2 + 36864);
#pragma unroll
                for (int mt = 0; mt < 2; ++mt) {
                    mma16816(acc[mt][2 * g],     ah[mt], wh[0], wh[1]);
                    mma16816(acc[mt][2 * g],     ah[mt], wl[0], wl[1]);
                    mma16816(acc[mt][2 * g],     al[mt], wh[0], wh[1]);
                    mma16816(acc[mt][2 * g + 1], ah[mt], wh[2], wh[3]);
                    mma16816(acc[mt][2 * g + 1], ah[mt], wl[2], wl[3]);
                    mma16816(acc[mt][2 * g + 1], al[mt], wh[2], wh[3]);
                }
            }
        }
        __syncthreads();   // all warps done reading Wbuf (and, on last iter, A)
    }

    // epilogue (A safe to overwrite: barrier above covers all readers)
    __nv_bfloat16* AHI = (__nv_bfloat16*)(sm + OFF_AHI);
    __nv_bfloat16* ALO = (__nv_bfloat16*)(sm + OFF_ALO);
    const float* scW = (const float*)(sm + OFF_CW);
    const float* saW = (const float*)(sm + OFF_AW);
    float* crow = (float*)(sm + OFF_CROW);

#pragma unroll
    for (int mt = 0; mt < 2; ++mt) {
        int r0 = mwarp * 32 + mt * 16 + (lane >> 2), r1 = r0 + 8;
        float pa0 = 0.f, pa1 = 0.f;
        float pc0[3] = {0.f, 0.f, 0.f}, pc1[3] = {0.f, 0.f, 0.f};
#pragma unroll
        for (int g = 0; g < 8; ++g) {
            int nb = nwarp * 64 + ((g < 4) ? g * 16 : 128 + (g - 4) * 16);
#pragma unroll
            for (int h = 0; h < 2; ++h) {
                int col = nb + h * 8 + (lane & 3) * 2;
                float* d = acc[mt][2 * g + h];
                float f0 = d[0] + bias[col], f1 = d[1] + bias[col + 1];
                float f2 = d[2] + bias[col], f3 = d[3] + bias[col + 1];
                if (MODE != 1) {
                    f0 = fmaxf(f0, 0.f); f1 = fmaxf(f1, 0.f);
                    f2 = fmaxf(f2, 0.f); f3 = fmaxf(f3, 0.f);
                }
                if (MODE <= 1) {
                    uint32_t h0, l0, h1, l1;
                    split2(f0, f1, h0, l0); split2(f2, f3, h1, l1);
                    *(uint32_t*)(AHI + r0 * ASTR + col) = h0;
                    *(uint32_t*)(ALO + r0 * ASTR + col) = l0;
                    *(uint32_t*)(AHI + r1 * ASTR + col) = h1;
                    *(uint32_t*)(ALO + r1 * ASTR + col) = l1;
                } else if (MODE == 2) {
                    pa0 += f0 * saW[col] + f1 * saW[col + 1];
                    pa1 += f2 * saW[col] + f3 * saW[col + 1];
                } else {
#pragma unroll
                    for (int j = 0; j < 3; ++j) {
                        pc0[j] += f0 * scW[col * 3 + j] + f1 * scW[(col + 1) * 3 + j];
                        pc1[j] += f2 * scW[col * 3 + j] + f3 * scW[(col + 1) * 3 + j];
                    }
                }
            }
        }
        if (MODE == 2) {
            pa0 += __shfl_xor_sync(~0u, pa0, 1); pa0 += __shfl_xor_sync(~0u, pa0, 2);
            pa1 += __shfl_xor_sync(~0u, pa1, 1); pa1 += __shfl_xor_sync(~0u, pa1, 2);
            if ((lane & 3) == 0) {
                atomicAdd(crow + r0 * 4 + 3, pa0);
                atomicAdd(crow + r1 * 4 + 3, pa1);
            }
        } else if (MODE == 3) {
#pragma unroll
            for (int j = 0; j < 3; ++j) {
                pc0[j] += __shfl_xor_sync(~0u, pc0[j], 1); pc0[j] += __shfl_xor_sync(~0u, pc0[j], 2);
                pc1[j] += __shfl_xor_sync(~0u, pc1[j], 1); pc1[j] += __shfl_xor_sync(~0u, pc1[j], 2);
            }
            if ((lane & 3) == 0) {
#pragma unroll
                for (int j = 0; j < 3; ++j) {
                    atomicAdd(crow + r0 * 4 + j, pc0[j]);
                    atomicAdd(crow + r1 * 4 + j, pc1[j]);
                }
            }
        }
    }
}

// ---------------- main kernel ----------------
__global__ void __launch_bounds__(256, 1)
mesh_main(const int* __restrict__ verts, const float* __restrict__ barys,
          const float* __restrict__ views, const float* __restrict__ emb,
          const float* __restrict__ b_proj, const float* __restrict__ view_b,
          const float* __restrict__ vert_b, float* __restrict__ out)
{
    extern __shared__ char sm[];
    uint32_t smb = smem_u32(sm);
    const int tid = threadIdx.x, lane = tid & 31, w = tid >> 5;
    const int base = blockIdx.x * 128;

    __nv_bfloat16* AHI = (__nv_bfloat16*)(sm + OFF_AHI);
    __nv_bfloat16* ALO = (__nv_bfloat16*)(sm + OFF_ALO);
    float* sbias = (float*)(sm + OFF_BIAS);
    float* scW   = (float*)(sm + OFF_CW);
    float* saW   = (float*)(sm + OFF_AW);
    float* crow  = (float*)(sm + OFF_CROW);
    float* sscl  = (float*)(sm + OFF_SCL);

    // stage constants
    for (int i = tid; i < 1280; i += 256) {
        float v;
        if (i < 512) v = vert_b[i];
        else if (i < 768) v = b_proj[i - 512];
        else v = view_b[i - 768];
        sbias[i] = v;
    }
    for (int i = tid; i < 1536; i += 256) scW[i] = g_cWd[i];
    if (tid < 256) saW[tid] = g_aWd[tid];
    if (tid < 128) {
        crow[tid * 4 + 0] = g_cbd[0]; crow[tid * 4 + 1] = g_cbd[1];
        crow[tid * 4 + 2] = g_cbd[2]; crow[tid * 4 + 3] = g_abd;
    }

    // ---- gather phase A: per-(row,vertex) norms ----
    for (int task = w; task < 384; task += 8) {
        int rr = task / 3, v = task - rr * 3;
        int grow = base + rr;
        int idx = verts[grow * 3 + v] + 1;
        const float* ep = emb + ((size_t)(grow & 7) * NTAB + (size_t)idx) * NC + lane * 8;
        float4 e0 = *(const float4*)ep, e1 = *(const float4*)(ep + 4);
        float ss = e0.x*e0.x + e0.y*e0.y + e0.z*e0.z + e0.w*e0.w
                 + e1.x*e1.x + e1.y*e1.y + e1.z*e1.z + e1.w*e1.w;
#pragma unroll
        for (int o = 16; o > 0; o >>= 1) ss += __shfl_xor_sync(~0u, ss, o);
        float s = barys[grow * 3 + v];
        float nrm = sqrtf(ss);
        if (nrm > 1.f) s *= 1.f / fmaxf(nrm, 1e-7f);
        if (lane == 0) sscl[task] = s;
    }
    __syncthreads();

    // ---- gather phase B: blend -> split bf16 into A bufs, color partials ----
    for (int r = w; r < 128; r += 8) {
        int grow = base + r;
        float v[8];
#pragma unroll
        for (int j = 0; j < 8; ++j) v[j] = 0.f;
#pragma unroll
        for (int vt = 0; vt < 3; ++vt) {
            float s = sscl[r * 3 + vt];
            int idx = verts[grow * 3 + vt] + 1;
            const float* ep = emb + ((size_t)(grow & 7) * NTAB + (size_t)idx) * NC + lane * 8;
            float4 e0 = *(const float4*)ep, e1 = *(const float4*)(ep + 4);
            v[0] += s*e0.x; v[1] += s*e0.y; v[2] += s*e0.z; v[3] += s*e0.w;
            v[4] += s*e1.x; v[5] += s*e1.y; v[6] += s*e1.z; v[7] += s*e1.w;
        }
        int cbase = lane * 8;
#pragma unroll
        for (int p = 0; p < 4; ++p) {
            uint32_t h, l;
            split2(v[2 * p], v[2 * p + 1], h, l);
            *(uint32_t*)(AHI + r * ASTR + cbase + 2 * p) = h;
            *(uint32_t*)(ALO + r * ASTR + cbase + 2 * p) = l;
        }
        float p0 = 0.f, p1 = 0.f, p2 = 0.f;
#pragma unroll
        for (int j = 0; j < 8; ++j) {
            const float* w3 = scW + (size_t)(256 + cbase + j) * 3;
            p0 += v[j] * w3[0]; p1 += v[j] * w3[1]; p2 += v[j] * w3[2];
        }
#pragma unroll
        for (int o = 16; o > 0; o >>= 1) {
            p0 += __shfl_xor_sync(~0u, p0, o);
            p1 += __shfl_xor_sync(~0u, p1, o);
            p2 += __shfl_xor_sync(~0u, p2, o);
        }
        if (lane == 0) {
            crow[r * 4 + 0] += p0; crow[r * 4 + 1] += p1; crow[r * 4 + 2] += p2;
        }
    }
    __syncthreads();

    // ---- vert branch ----
    do_layer<256, 0>(sm, smb, g_wT[0][0], g_wT[0][1], sbias);        // L3 relu
    __syncthreads();
    do_layer<256, 2>(sm, smb, g_wT[1][0], g_wT[1][1], sbias + 256);  // L4 -> alpha
    __syncthreads();

    // ---- sincos -> A bufs (K padded to 64) ----
    if (tid < 128) {
        int row = base + tid;
        float x0 = views[row * 3], x1 = views[row * 3 + 1], x2 = views[row * 3 + 2];
        float em[36];
#pragma unroll
        for (int l = 0; l < 6; ++l) {
            float f = (float)(1 << l);
            em[l * 6 + 0] = sinf(f * x0); em[l * 6 + 1] = sinf(f * x1); em[l * 6 + 2] = sinf(f * x2);
            em[l * 6 + 3] = cosf(f * x0); em[l * 6 + 4] = cosf(f * x1); em[l * 6 + 5] = cosf(f * x2);
        }
#pragma unroll
        for (int p = 0; p < 18; ++p) {
            uint32_t h, l;
            split2(em[2 * p], em[2 * p + 1], h, l);
            *(uint32_t*)(AHI + tid * ASTR + 2 * p) = h;
            *(uint32_t*)(ALO + tid * ASTR + 2 * p) = l;
        }
#pragma unroll
        for (int p = 18; p < 32; ++p) {
            *(uint32_t*)(AHI + tid * ASTR + 2 * p) = 0u;
            *(uint32_t*)(ALO + tid * ASTR + 2 * p) = 0u;
        }
    }
    __syncthreads();

    // ---- view branch ----
    do_layer<64, 1>(sm, smb, g_wP[0], g_wP[1], sbias + 512);          // proj, no relu
    __syncthreads();
    do_layer<256, 0>(sm, smb, g_wT[2][0], g_wT[2][1], sbias + 768);   // L1 relu
    __syncthreads();
    do_layer<256, 3>(sm, smb, g_wT[3][0], g_wT[3][1], sbias + 1024);  // L2 -> color
    __syncthreads();

    if (tid < 128) {
        float4 ov = make_float4(crow[tid * 4 + 0], crow[tid * 4 + 1],
                                crow[tid * 4 + 2], crow[tid * 4 + 3]);
        *(float4*)(out + (size_t)(base + tid) * 4) = ov;
    }
}

extern "C" void kernel_launch(void* const* d_in, const int* in_sizes, int n_in,
                              void* d_out, int out_size)
{
    const int*   verts  = (const int*)  d_in[0];
    const float* barys  = (const float*)d_in[1];
    const float* views  = (const float*)d_in[2];
    const float* emb    = (const float*)d_in[3];
    const float* w_proj = (const float*)d_in[4];
    const float* b_proj = (const float*)d_in[5];
    const float* view_W = (const float*)d_in[6];
    const float* view_b = (const float*)d_in[7];
    const float* vert_W = (const float*)d_in[8];
    const float* vert_b = (const float*)d_in[9];
    const float* aW1    = (const float*)d_in[10];
    const float* ab1    = (const float*)d_in[11];
    const float* aW2    = (const float*)d_in[12];
    const float* ab2    = (const float*)d_in[13];
    const float* cW1    = (const float*)d_in[14];
    const float* cb1    = (const float*)d_in[15];
    const float* cW2    = (const float*)d_in[16];
    const float* cb2    = (const float*)d_in[17];
    float* out = (float*)d_out;

    prep_kernel<<<1096, 256>>>(w_proj, view_W, vert_W, aW1, ab1, aW2, ab2,
                               cW1, cb1, cW2, cb2);

    cudaFuncSetAttribute(mesh_main, cudaFuncAttributeMaxDynamicSharedMemorySize, SM_REQ);
    mesh_main<<<NROWS / 128, 256, SM_REQ>>>(verts, barys, views, emb,
                                            b_proj, view_b, vert_b, out);
}

// round 7
// speedup vs baseline: 4.0728x; 1.0172x over previous
#include <cuda_runtime.h>
#include <cuda_bf16.h>
#include <math.h>
#include <stdint.h>

#define NROWS 262144
#define NTAB  50001
#define NC    256

// SMEM byte offsets
#define OFF_AHI  0            // 128 x 264 bf16 = 67584
#define OFF_ALO  67584        // -> 135168
#define OFF_WBUF 135168       // 2 x 40960 (each: hi 20480 | lo 20480) -> 217088
#define OFF_BIAS 217088       // 1280 floats -> 222208
#define OFF_CROW 222208       // 128 x 4 floats -> 224256
#define OFF_SCL  224256       // 384 floats -> 225792
#define SM_REQ   225792
#define ASTR 264
#define WCH  40               // chunk W stride in halves (80 B rows)

__device__ __align__(16) __nv_bfloat16 g_wT[4][2][65536]; // [vert0,vert1,view0,view1][hi,lo][n*256+k]
__device__ __align__(16) __nv_bfloat16 g_wP[2][16384];    // proj [hi,lo][n*64+k]
__device__ float g_cWd[1536], g_aWd[256], g_cbd[3], g_abd;

// ---------------- low-level helpers ----------------
__device__ __forceinline__ uint32_t smem_u32(const void* p) {
    uint32_t a;
    asm("{ .reg .u64 t; cvta.to.shared.u64 t, %1; cvt.u32.u64 %0, t; }" : "=r"(a) : "l"(p));
    return a;
}
__device__ __forceinline__ void ldsm4(uint32_t r[4], uint32_t a) {
    asm volatile("ldmatrix.sync.aligned.m8n8.x4.shared.b16 {%0,%1,%2,%3}, [%4];"
        : "=r"(r[0]), "=r"(r[1]), "=r"(r[2]), "=r"(r[3]) : "r"(a));
}
__device__ __forceinline__ void mma16816(float c[4], const uint32_t a[4], uint32_t b0, uint32_t b1) {
    asm volatile("mma.sync.aligned.m16n8k16.row.col.f32.bf16.bf16.f32 "
        "{%0,%1,%2,%3},{%4,%5,%6,%7},{%8,%9},{%0,%1,%2,%3};"
        : "+f"(c[0]), "+f"(c[1]), "+f"(c[2]), "+f"(c[3])
        : "r"(a[0]), "r"(a[1]), "r"(a[2]), "r"(a[3]), "r"(b0), "r"(b1));
}
__device__ __forceinline__ void cp16(uint32_t d, const void* s) {
    asm volatile("cp.async.cg.shared.global [%0], [%1], 16;" :: "r"(d), "l"(s));
}
__device__ __forceinline__ void split2(float f0, float f1, uint32_t &h, uint32_t &l) {
    __nv_bfloat162 hh = __floats2bfloat162_rn(f0, f1);
    float r0 = f0 - __bfloat162float(hh.x);
    float r1 = f1 - __bfloat162float(hh.y);
    __nv_bfloat162 ll = __floats2bfloat162_rn(r0, r1);
    h = *(uint32_t*)&hh; l = *(uint32_t*)&ll;
}

// copy one 32-K chunk (hi+lo, 256 n-rows) into a weight buffer, commit the group
__device__ __forceinline__ void copy_chunk32(uint32_t wdst, const __nv_bfloat16* srcHi,
        const __nv_bfloat16* srcLo, int kfull, int c, int tid)
{
#pragma unroll
    for (int q = 0; q < 8; ++q) {
        int e = q * 256 + tid;
        int mat = e >> 10, rem = e & 1023, r = rem >> 2, s = rem & 3;
        const __nv_bfloat16* src = (mat ? srcLo : srcHi) + r * kfull + c * 32 + s * 8;
        cp16(wdst + mat * 20480 + (uint32_t)(r * 80 + s * 16), src);
    }
    asm volatile("cp.async.commit_group;");
}

// ---------------- prep kernel ----------------
__global__ void prep_kernel(const float* __restrict__ w_proj, const float* __restrict__ view_W,
                            const float* __restrict__ vert_W,
                            const float* __restrict__ aW1, const float* __restrict__ ab1,
                            const float* __restrict__ aW2, const float* __restrict__ ab2,
                            const float* __restrict__ cW1, const float* __restrict__ cb1,
                            const float* __restrict__ cW2, const float* __restrict__ cb2)
{
    int t = blockIdx.x * blockDim.x + threadIdx.x;
    if (t < 262144) {
        int layer = t >> 16, e = t & 65535, n = e >> 8, k = e & 255;
        const float* W = (layer < 2) ? (vert_W + layer * 65536) : (view_W + (layer - 2) * 65536);
        float w = W[k * 256 + n];
        __nv_bfloat16 hb = __float2bfloat16(w);
        g_wT[layer][0][n * 256 + k] = hb;
        g_wT[layer][1][n * 256 + k] = __float2bfloat16(w - __bfloat162float(hb));
    } else if (t < 262144 + 16384) {
        int e = t - 262144, n = e >> 6, k = e & 63;
        float w = (k < 36) ? w_proj[k * 256 + n] : 0.f;
        __nv_bfloat16 hb = __float2bfloat16(w);
        g_wP[0][n * 64 + k] = hb;
        g_wP[1][n * 64 + k] = __float2bfloat16(w - __bfloat162float(hb));
    } else if (t < 262144 + 16384 + 1536) {
        int e = t - 262144 - 16384, kk = e / 3, j = e - kk * 3;
        float s = 0.f;
        for (int m = 0; m < 512; ++m) s += cW1[kk * 512 + m] * cW2[m * 3 + j];
        g_cWd[e] = s;
    } else if (t < 262144 + 16384 + 1536 + 3) {
        int j = t - 262144 - 16384 - 1536;
        float s = cb2[j];
        for (int m = 0; m < 512; ++m) s += cb1[m] * cW2[m * 3 + j];
        g_cbd[j] = s;
    } else if (t < 262144 + 16384 + 1536 + 3 + 256) {
        int kk = t - 262144 - 16384 - 1536 - 3;
        float s = 0.f;
        for (int m = 0; m < 256; ++m) s += aW1[kk * 256 + m] * aW2[m];
        g_aWd[kk] = s;
    } else if (t == 262144 + 16384 + 1536 + 3 + 256) {
        float s = ab2[0];
        for (int m = 0; m < 256; ++m) s += ab1[m] * aW2[m];
        g_abd = s;
    }
}

// ---------------- fused pipelined layer ----------------
// MODE 0: store relu; 1: store no-relu; 2: alpha head (relu); 3: color head (relu)
// Precondition: this layer's chunk 0 copy already committed (1 group pending).
// Postcondition (if nxHi): next layer's chunk 0 committed (1 group pending).
template<int KFULL, int MODE>
__device__ void do_layer(char* sm, uint32_t smb, const __nv_bfloat16* __restrict__ WgHi,
    const __nv_bfloat16* __restrict__ WgLo, const float* __restrict__ bias,
    const __nv_bfloat16* nxHi, const __nv_bfloat16* nxLo, int nxK)
{
    const int tid = threadIdx.x, lane = tid & 31, w = tid >> 5;
    const int mwarp = w >> 1, nwarp = w & 1;
    const int rowin = lane & 7, tsel = lane >> 3;

    float acc[2][16][4];
#pragma unroll
    for (int mt = 0; mt < 2; ++mt)
#pragma unroll
        for (int nt = 0; nt < 16; ++nt)
#pragma unroll
            for (int j = 0; j < 4; ++j) acc[mt][nt][j] = 0.f;

    uint32_t aoffH[2], aoffL[2];
#pragma unroll
    for (int mt = 0; mt < 2; ++mt) {
        int row = mwarp * 32 + mt * 16 + rowin + (tsel & 1) * 8;
        int ks = (tsel >> 1) * 8;
        aoffH[mt] = smb + OFF_AHI + (uint32_t)(row * ASTR + ks) * 2;
        aoffL[mt] = smb + OFF_ALO + (uint32_t)(row * ASTR + ks) * 2;
    }
    const int rowB = rowin + (tsel >> 1) * 8;
    const int ksB  = (tsel & 1) * 8;
    uint32_t bof[8];
#pragma unroll
    for (int g = 0; g < 8; ++g) {
        int nb = nwarp * 64 + ((g < 4) ? g * 16 : 128 + (g - 4) * 16);
        bof[g] = (uint32_t)((nb + rowB) * WCH + ksB) * 2;
    }
    const uint32_t wbase = smb + OFF_WBUF;
    const int nch = KFULL / 32;

    copy_chunk32(wbase + 40960, WgHi, WgLo, KFULL, 1, tid);   // chunk 1 -> buf1

    for (int c = 0; c < nch; ++c) {
        asm volatile("cp.async.wait_group 1;" ::: "memory");
        __syncthreads();                       // chunk c visible; prev epilogue/A writes ordered
        const uint32_t wb = wbase + (uint32_t)(c & 1) * 40960;
#pragma unroll
        for (int kk = 0; kk < 2; ++kk) {
            int kg2 = (c * 32 + kk * 16) * 2;
            uint32_t ah[2][4], al[2][4];
            ldsm4(ah[0], aoffH[0] + kg2); ldsm4(ah[1], aoffH[1] + kg2);
            ldsm4(al[0], aoffL[0] + kg2); ldsm4(al[1], aoffL[1] + kg2);
#pragma unroll
            for (int g = 0; g < 8; ++g) {
                uint32_t wh[4], wl[4];
                ldsm4(wh, wb + bof[g] + kk * 32);
                ldsm4(wl, wb + bof[g] + 20480 + kk * 32);
#pragma unroll
                for (int mt = 0; mt < 2; ++mt) {
                    mma16816(acc[mt][2 * g],     ah[mt], wh[0], wh[1]);
                    mma16816(acc[mt][2 * g],     ah[mt], wl[0], wl[1]);
                    mma16816(acc[mt][2 * g],     al[mt], wh[0], wh[1]);
                    mma16816(acc[mt][2 * g + 1], ah[mt], wh[2], wh[3]);
                    mma16816(acc[mt][2 * g + 1], ah[mt], wl[2], wl[3]);
                    mma16816(acc[mt][2 * g + 1], al[mt], wh[2], wh[3]);
                }
            }
        }
        __syncthreads();                       // all warps done reading buf[c&1]
        if (c + 2 < nch) {
            copy_chunk32(wbase + (uint32_t)(c & 1) * 40960, WgHi, WgLo, KFULL, c + 2, tid);
        } else if (c + 2 == nch) {
            if (nxHi) copy_chunk32(wbase, nxHi, nxLo, nxK, 0, tid);
            else      asm volatile("cp.async.commit_group;");   // keep group count aligned
        }
    }

    // ---- epilogue ----
    __nv_bfloat16* AHI = (__nv_bfloat16*)(sm + OFF_AHI);
    __nv_bfloat16* ALO = (__nv_bfloat16*)(sm + OFF_ALO);
    float* crow = (float*)(sm + OFF_CROW);

#pragma unroll
    for (int mt = 0; mt < 2; ++mt) {
        int r0 = mwarp * 32 + mt * 16 + (lane >> 2), r1 = r0 + 8;
        float pa0 = 0.f, pa1 = 0.f;
        float pc0[3] = {0.f, 0.f, 0.f}, pc1[3] = {0.f, 0.f, 0.f};
#pragma unroll
        for (int g = 0; g < 8; ++g) {
            int nb = nwarp * 64 + ((g < 4) ? g * 16 : 128 + (g - 4) * 16);
#pragma unroll
            for (int h = 0; h < 2; ++h) {
                int col = nb + h * 8 + (lane & 3) * 2;
                float* d = acc[mt][2 * g + h];
                float f0 = d[0] + bias[col], f1 = d[1] + bias[col + 1];
                float f2 = d[2] + bias[col], f3 = d[3] + bias[col + 1];
                if (MODE != 1) {
                    f0 = fmaxf(f0, 0.f); f1 = fmaxf(f1, 0.f);
                    f2 = fmaxf(f2, 0.f); f3 = fmaxf(f3, 0.f);
                }
                if (MODE <= 1) {
                    uint32_t h0, l0, h1, l1;
                    split2(f0, f1, h0, l0); split2(f2, f3, h1, l1);
                    *(uint32_t*)(AHI + r0 * ASTR + col) = h0;
                    *(uint32_t*)(ALO + r0 * ASTR + col) = l0;
                    *(uint32_t*)(AHI + r1 * ASTR + col) = h1;
                    *(uint32_t*)(ALO + r1 * ASTR + col) = l1;
                } else if (MODE == 2) {
                    float w0 = __ldg(g_aWd + col), w1 = __ldg(g_aWd + col + 1);
                    pa0 += f0 * w0 + f1 * w1;
                    pa1 += f2 * w0 + f3 * w1;
                } else {
#pragma unroll
                    for (int j = 0; j < 3; ++j) {
                        float w0 = __ldg(g_cWd + col * 3 + j), w1 = __ldg(g_cWd + (col + 1) * 3 + j);
                        pc0[j] += f0 * w0 + f1 * w1;
                        pc1[j] += f2 * w0 + f3 * w1;
                    }
                }
            }
        }
        if (MODE == 2) {
            pa0 += __shfl_xor_sync(~0u, pa0, 1); pa0 += __shfl_xor_sync(~0u, pa0, 2);
            pa1 += __shfl_xor_sync(~0u, pa1, 1); pa1 += __shfl_xor_sync(~0u, pa1, 2);
            if ((lane & 3) == 0) {
                atomicAdd(crow + r0 * 4 + 3, pa0);
                atomicAdd(crow + r1 * 4 + 3, pa1);
            }
        } else if (MODE == 3) {
#pragma unroll
            for (int j = 0; j < 3; ++j) {
                pc0[j] += __shfl_xor_sync(~0u, pc0[j], 1); pc0[j] += __shfl_xor_sync(~0u, pc0[j], 2);
                pc1[j] += __shfl_xor_sync(~0u, pc1[j], 1); pc1[j] += __shfl_xor_sync(~0u, pc1[j], 2);
            }
            if ((lane & 3) == 0) {
#pragma unroll
                for (int j = 0; j < 3; ++j) {
                    atomicAdd(crow + r0 * 4 + j, pc0[j]);
                    atomicAdd(crow + r1 * 4 + j, pc1[j]);
                }
            }
        }
    }
}

// ---------------- main kernel ----------------
__global__ void __launch_bounds__(256, 1)
mesh_main(const int* __restrict__ verts, const float* __restrict__ barys,
          const float* __restrict__ views, const float* __restrict__ emb,
          const float* __restrict__ b_proj, const float* __restrict__ view_b,
          const float* __restrict__ vert_b, float* __restrict__ out)
{
    extern __shared__ char sm[];
    uint32_t smb = smem_u32(sm);
    const int tid = threadIdx.x, lane = tid & 31, w = tid >> 5;
    const int base = blockIdx.x * 128;

    __nv_bfloat16* AHI = (__nv_bfloat16*)(sm + OFF_AHI);
    __nv_bfloat16* ALO = (__nv_bfloat16*)(sm + OFF_ALO);
    float* sbias = (float*)(sm + OFF_BIAS);
    float* crow  = (float*)(sm + OFF_CROW);
    float* sscl  = (float*)(sm + OFF_SCL);

    // prefetch first weight chunk immediately (overlaps gather)
    copy_chunk32(smb + OFF_WBUF, g_wT[0][0], g_wT[0][1], 256, 0, tid);

    // stage constants
    for (int i = tid; i < 1280; i += 256) {
        float v;
        if (i < 512) v = vert_b[i];
        else if (i < 768) v = b_proj[i - 512];
        else v = view_b[i - 768];
        sbias[i] = v;
    }
    if (tid < 128) {
        crow[tid * 4 + 0] = g_cbd[0]; crow[tid * 4 + 1] = g_cbd[1];
        crow[tid * 4 + 2] = g_cbd[2]; crow[tid * 4 + 3] = g_abd;
    }

    // ---- gather phase A: per-(row,vertex) norms ----
    for (int task = w; task < 384; task += 8) {
        int rr = task / 3, v = task - rr * 3;
        int grow = base + rr;
        int idx = verts[grow * 3 + v] + 1;
        const float* ep = emb + ((size_t)(grow & 7) * NTAB + (size_t)idx) * NC + lane * 8;
        float4 e0 = *(const float4*)ep, e1 = *(const float4*)(ep + 4);
        float ss = e0.x*e0.x + e0.y*e0.y + e0.z*e0.z + e0.w*e0.w
                 + e1.x*e1.x + e1.y*e1.y + e1.z*e1.z + e1.w*e1.w;
#pragma unroll
        for (int o = 16; o > 0; o >>= 1) ss += __shfl_xor_sync(~0u, ss, o);
        float s = barys[grow * 3 + v];
        float nrm = sqrtf(ss);
        if (nrm > 1.f) s *= 1.f / fmaxf(nrm, 1e-7f);
        if (lane == 0) sscl[task] = s;
    }
    __syncthreads();

    // ---- gather phase B: blend -> split bf16 into A bufs, color partials ----
    for (int r = w; r < 128; r += 8) {
        int grow = base + r;
        float v[8];
#pragma unroll
        for (int j = 0; j < 8; ++j) v[j] = 0.f;
#pragma unroll
        for (int vt = 0; vt < 3; ++vt) {
            float s = sscl[r * 3 + vt];
            int idx = verts[grow * 3 + vt] + 1;
            const float* ep = emb + ((size_t)(grow & 7) * NTAB + (size_t)idx) * NC + lane * 8;
            float4 e0 = *(const float4*)ep, e1 = *(const float4*)(ep + 4);
            v[0] += s*e0.x; v[1] += s*e0.y; v[2] += s*e0.z; v[3] += s*e0.w;
            v[4] += s*e1.x; v[5] += s*e1.y; v[6] += s*e1.z; v[7] += s*e1.w;
        }
        int cbase = lane * 8;
#pragma unroll
        for (int p = 0; p < 4; ++p) {
            uint32_t h, l;
            split2(v[2 * p], v[2 * p + 1], h, l);
            *(uint32_t*)(AHI + r * ASTR + cbase + 2 * p) = h;
            *(uint32_t*)(ALO + r * ASTR + cbase + 2 * p) = l;
        }
        float p0 = 0.f, p1 = 0.f, p2 = 0.f;
#pragma unroll
        for (int j = 0; j < 8; ++j) {
            const float* w3 = g_cWd + (size_t)(256 + cbase + j) * 3;
            p0 += v[j] * __ldg(w3); p1 += v[j] * __ldg(w3 + 1); p2 += v[j] * __ldg(w3 + 2);
        }
#pragma unroll
        for (int o = 16; o > 0; o >>= 1) {
            p0 += __shfl_xor_sync(~0u, p0, o);
            p1 += __shfl_xor_sync(~0u, p1, o);
            p2 += __shfl_xor_sync(~0u, p2, o);
        }
        if (lane == 0) {
            crow[r * 4 + 0] += p0; crow[r * 4 + 1] += p1; crow[r * 4 + 2] += p2;
        }
    }

    // ---- vert branch ----
    do_layer<256, 0>(sm, smb, g_wT[0][0], g_wT[0][1], sbias,       g_wT[1][0], g_wT[1][1], 256);
    do_layer<256, 2>(sm, smb, g_wT[1][0], g_wT[1][1], sbias + 256, g_wP[0],    g_wP[1],    64);

    // ---- sincos -> A bufs (K padded to 64) ----
    if (tid < 128) {
        int row = base + tid;
        float x0 = views[row * 3], x1 = views[row * 3 + 1], x2 = views[row * 3 + 2];
        float em[36];
#pragma unroll
        for (int l = 0; l < 6; ++l) {
            float f = (float)(1 << l);
            em[l * 6 + 0] = sinf(f * x0); em[l * 6 + 1] = sinf(f * x1); em[l * 6 + 2] = sinf(f * x2);
            em[l * 6 + 3] = cosf(f * x0); em[l * 6 + 4] = cosf(f * x1); em[l * 6 + 5] = cosf(f * x2);
        }
#pragma unroll
        for (int p = 0; p < 18; ++p) {
            uint32_t h, l;
            split2(em[2 * p], em[2 * p + 1], h, l);
            *(uint32_t*)(AHI + tid * ASTR + 2 * p) = h;
            *(uint32_t*)(ALO + tid * ASTR + 2 * p) = l;
        }
#pragma unroll
        for (int p = 18; p < 32; ++p) {
            *(uint32_t*)(AHI + tid * ASTR + 2 * p) = 0u;
            *(uint32_t*)(ALO + tid * ASTR + 2 * p) = 0u;
        }
    }

    // ---- view branch ----
    do_layer<64, 1>(sm, smb, g_wP[0], g_wP[1], sbias + 512,          g_wT[2][0], g_wT[2][1], 256);
    do_layer<256, 0>(sm, smb, g_wT[2][0], g_wT[2][1], sbias + 768,   g_wT[3][0], g_wT[3][1], 256);
    do_layer<256, 3>(sm, smb, g_wT[3][0], g_wT[3][1], sbias + 1024,  (const __nv_bfloat16*)0, (const __nv_bfloat16*)0, 0);

    __syncthreads();
    if (tid < 128) {
        float4 ov = make_float4(crow[tid * 4 + 0], crow[tid * 4 + 1],
                                crow[tid * 4 + 2], crow[tid * 4 + 3]);
        *(float4*)(out + (size_t)(base + tid) * 4) = ov;
    }
}

extern "C" void kernel_launch(void* const* d_in, const int* in_sizes, int n_in,
                              void* d_out, int out_size)
{
    const int*   verts  = (const int*)  d_in[0];
    const float* barys  = (const float*)d_in[1];
    const float* views  = (const float*)d_in[2];
    const float* emb    = (const float*)d_in[3];
    const float* w_proj = (const float*)d_in[4];
    const float* b_proj = (const float*)d_in[5];
    const float* view_W = (const float*)d_in[6];
    const float* view_b = (const float*)d_in[7];
    const float* vert_W = (const float*)d_in[8];
    const float* vert_b = (const float*)d_in[9];
    const float* aW1    = (const float*)d_in[10];
    const float* ab1    = (const float*)d_in[11];
    const float* aW2    = (const float*)d_in[12];
    const float* ab2    = (const float*)d_in[13];
    const float* cW1    = (const float*)d_in[14];
    const float* cb1    = (const float*)d_in[15];
    const float* cW2    = (const float*)d_in[16];
    const float* cb2    = (const float*)d_in[17];
    float* out = (float*)d_out;

    prep_kernel<<<1096, 256>>>(w_proj, view_W, vert_W, aW1, ab1, aW2, ab2,
                               cW1, cb1, cW2, cb2);

    cudaFuncSetAttribute(mesh_main, cudaFuncAttributeMaxDynamicSharedMemorySize, SM_REQ);
    mesh_main<<<NROWS / 128, 256, SM_REQ>>>(verts, barys, views, emb,
                                            b_proj, view_b, vert_b, out);
}

// round 8
// speedup vs baseline: 5.2068x; 1.2784x over previous
#include <cuda_runtime.h>
#include <cuda_bf16.h>
#include <math.h>
#include <stdint.h>

#define NROWS 262144
#define NTAB  50001
#define NC    256
#define NTHR  512

// SMEM byte offsets
#define OFF_AHI  0            // 128 x 264 bf16 = 67584
#define OFF_ALO  67584        // -> 135168
#define OFF_WBUF 135168       // 2 x 40960 (each: hi 20480 | lo 20480) -> 217088
#define OFF_BIAS 217088       // 1280 floats -> 222208
#define OFF_CROW 222208       // 128 x 4 floats -> 224256
#define OFF_SCL  224256       // 384 floats -> 225792
#define SM_REQ   225792
#define ASTR 264
#define WCH  40               // chunk W stride in halves (80 B rows)

__device__ __align__(16) __nv_bfloat16 g_wT[4][2][65536]; // [vert0,vert1,view0,view1][hi,lo][n*256+k]
__device__ __align__(16) __nv_bfloat16 g_wP[2][16384];    // proj [hi,lo][n*64+k]
__device__ float g_cWd[1536], g_aWd[256], g_cbd[3], g_abd;

// ---------------- low-level helpers ----------------
__device__ __forceinline__ uint32_t smem_u32(const void* p) {
    uint32_t a;
    asm("{ .reg .u64 t; cvta.to.shared.u64 t, %1; cvt.u32.u64 %0, t; }" : "=r"(a) : "l"(p));
    return a;
}
__device__ __forceinline__ void ldsm4(uint32_t r[4], uint32_t a) {
    asm volatile("ldmatrix.sync.aligned.m8n8.x4.shared.b16 {%0,%1,%2,%3}, [%4];"
        : "=r"(r[0]), "=r"(r[1]), "=r"(r[2]), "=r"(r[3]) : "r"(a));
}
__device__ __forceinline__ void mma16816(float c[4], const uint32_t a[4], uint32_t b0, uint32_t b1) {
    asm volatile("mma.sync.aligned.m16n8k16.row.col.f32.bf16.bf16.f32 "
        "{%0,%1,%2,%3},{%4,%5,%6,%7},{%8,%9},{%0,%1,%2,%3};"
        : "+f"(c[0]), "+f"(c[1]), "+f"(c[2]), "+f"(c[3])
        : "r"(a[0]), "r"(a[1]), "r"(a[2]), "r"(a[3]), "r"(b0), "r"(b1));
}
__device__ __forceinline__ void cp16(uint32_t d, const void* s) {
    asm volatile("cp.async.cg.shared.global [%0], [%1], 16;" :: "r"(d), "l"(s));
}
__device__ __forceinline__ void split2(float f0, float f1, uint32_t &h, uint32_t &l) {
    __nv_bfloat162 hh = __floats2bfloat162_rn(f0, f1);
    float r0 = f0 - __bfloat162float(hh.x);
    float r1 = f1 - __bfloat162float(hh.y);
    __nv_bfloat162 ll = __floats2bfloat162_rn(r0, r1);
    h = *(uint32_t*)&hh; l = *(uint32_t*)&ll;
}

// copy one 32-K chunk (hi+lo, 256 n-rows) into a weight buffer, commit the group
__device__ __forceinline__ void copy_chunk32(uint32_t wdst, const __nv_bfloat16* srcHi,
        const __nv_bfloat16* srcLo, int kfull, int c, int tid)
{
#pragma unroll
    for (int q = 0; q < 4; ++q) {
        int e = q * NTHR + tid;
        int mat = e >> 10, rem = e & 1023, r = rem >> 2, s = rem & 3;
        const __nv_bfloat16* src = (mat ? srcLo : srcHi) + r * kfull + c * 32 + s * 8;
        cp16(wdst + mat * 20480 + (uint32_t)(r * 80 + s * 16), src);
    }
    asm volatile("cp.async.commit_group;");
}

// ---------------- prep kernel ----------------
__global__ void prep_kernel(const float* __restrict__ w_proj, const float* __restrict__ view_W,
                            const float* __restrict__ vert_W,
                            const float* __restrict__ aW1, const float* __restrict__ ab1,
                            const float* __restrict__ aW2, const float* __restrict__ ab2,
                            const float* __restrict__ cW1, const float* __restrict__ cb1,
                            const float* __restrict__ cW2, const float* __restrict__ cb2)
{
    int t = blockIdx.x * blockDim.x + threadIdx.x;
    if (t < 262144) {
        int layer = t >> 16, e = t & 65535, n = e >> 8, k = e & 255;
        const float* W = (layer < 2) ? (vert_W + layer * 65536) : (view_W + (layer - 2) * 65536);
        float w = W[k * 256 + n];
        __nv_bfloat16 hb = __float2bfloat16(w);
        g_wT[layer][0][n * 256 + k] = hb;
        g_wT[layer][1][n * 256 + k] = __float2bfloat16(w - __bfloat162float(hb));
    } else if (t < 262144 + 16384) {
        int e = t - 262144, n = e >> 6, k = e & 63;
        float w = (k < 36) ? w_proj[k * 256 + n] : 0.f;
        __nv_bfloat16 hb = __float2bfloat16(w);
        g_wP[0][n * 64 + k] = hb;
        g_wP[1][n * 64 + k] = __float2bfloat16(w - __bfloat162float(hb));
    } else if (t < 262144 + 16384 + 1536) {
        int e = t - 262144 - 16384, kk = e / 3, j = e - kk * 3;
        float s = 0.f;
        for (int m = 0; m < 512; ++m) s += cW1[kk * 512 + m] * cW2[m * 3 + j];
        g_cWd[e] = s;
    } else if (t < 262144 + 16384 + 1536 + 3) {
        int j = t - 262144 - 16384 - 1536;
        float s = cb2[j];
        for (int m = 0; m < 512; ++m) s += cb1[m] * cW2[m * 3 + j];
        g_cbd[j] = s;
    } else if (t < 262144 + 16384 + 1536 + 3 + 256) {
        int kk = t - 262144 - 16384 - 1536 - 3;
        float s = 0.f;
        for (int m = 0; m < 256; ++m) s += aW1[kk * 256 + m] * aW2[m];
        g_aWd[kk] = s;
    } else if (t == 262144 + 16384 + 1536 + 3 + 256) {
        float s = ab2[0];
        for (int m = 0; m < 256; ++m) s += ab1[m] * aW2[m];
        g_abd = s;
    }
}

// ---------------- fused pipelined layer (16 warps: 4M x 4N) ----------------
// MODE 0: store relu; 1: store no-relu; 2: alpha head (relu); 3: color head (relu)
template<int KFULL, int MODE>
__device__ void do_layer(char* sm, uint32_t smb, const __nv_bfloat16* __restrict__ WgHi,
    const __nv_bfloat16* __restrict__ WgLo, const float* __restrict__ bias,
    const __nv_bfloat16* nxHi, const __nv_bfloat16* nxLo, int nxK)
{
    const int tid = threadIdx.x, lane = tid & 31, w = tid >> 5;
    const int mwarp = w >> 2, nwarp = w & 3;
    const int rowin = lane & 7, tsel = lane >> 3;

    float acc[2][8][4];
#pragma unroll
    for (int mt = 0; mt < 2; ++mt)
#pragma unroll
        for (int nt = 0; nt < 8; ++nt)
#pragma unroll
            for (int j = 0; j < 4; ++j) acc[mt][nt][j] = 0.f;

    uint32_t aoffH[2], aoffL[2];
#pragma unroll
    for (int mt = 0; mt < 2; ++mt) {
        int row = mwarp * 32 + mt * 16 + rowin + (tsel & 1) * 8;
        int ks = (tsel >> 1) * 8;
        aoffH[mt] = smb + OFF_AHI + (uint32_t)(row * ASTR + ks) * 2;
        aoffL[mt] = smb + OFF_ALO + (uint32_t)(row * ASTR + ks) * 2;
    }
    const int rowB = rowin + (tsel >> 1) * 8;
    const int ksB  = (tsel & 1) * 8;
    uint32_t bof[4];
#pragma unroll
    for (int g = 0; g < 4; ++g) {
        int nb = nwarp * 64 + g * 16;
        bof[g] = (uint32_t)((nb + rowB) * WCH + ksB) * 2;
    }
    const uint32_t wbase = smb + OFF_WBUF;
    const int nch = KFULL / 32;

    copy_chunk32(wbase + 40960, WgHi, WgLo, KFULL, 1, tid);   // chunk 1 -> buf1

    for (int c = 0; c < nch; ++c) {
        asm volatile("cp.async.wait_group 1;" ::: "memory");
        __syncthreads();
        const uint32_t wb = wbase + (uint32_t)(c & 1) * 40960;
#pragma unroll
        for (int kk = 0; kk < 2; ++kk) {
            int kg2 = (c * 32 + kk * 16) * 2;
            uint32_t ah[2][4], al[2][4];
            ldsm4(ah[0], aoffH[0] + kg2); ldsm4(ah[1], aoffH[1] + kg2);
            ldsm4(al[0], aoffL[0] + kg2); ldsm4(al[1], aoffL[1] + kg2);
#pragma unroll
            for (int g = 0; g < 4; ++g) {
                uint32_t wh[4], wl[4];
                ldsm4(wh, wb + bof[g] + kk * 32);
                ldsm4(wl, wb + bof[g] + 20480 + kk * 32);
#pragma unroll
                for (int mt = 0; mt < 2; ++mt) {
                    mma16816(acc[mt][2 * g],     ah[mt], wh[0], wh[1]);
                    mma16816(acc[mt][2 * g],     ah[mt], wl[0], wl[1]);
                    mma16816(acc[mt][2 * g],     al[mt], wh[0], wh[1]);
                    mma16816(acc[mt][2 * g + 1], ah[mt], wh[2], wh[3]);
                    mma16816(acc[mt][2 * g + 1], ah[mt], wl[2], wl[3]);
                    mma16816(acc[mt][2 * g + 1], al[mt], wh[2], wh[3]);
                }
            }
        }
        __syncthreads();
        if (c + 2 < nch) {
            copy_chunk32(wbase + (uint32_t)(c & 1) * 40960, WgHi, WgLo, KFULL, c + 2, tid);
        } else if (c + 2 == nch) {
            if (nxHi) copy_chunk32(wbase, nxHi, nxLo, nxK, 0, tid);
            else      asm volatile("cp.async.commit_group;");
        }
    }

    // ---- epilogue ----
    __nv_bfloat16* AHI = (__nv_bfloat16*)(sm + OFF_AHI);
    __nv_bfloat16* ALO = (__nv_bfloat16*)(sm + OFF_ALO);
    float* crow = (float*)(sm + OFF_CROW);

#pragma unroll
    for (int mt = 0; mt < 2; ++mt) {
        int r0 = mwarp * 32 + mt * 16 + (lane >> 2), r1 = r0 + 8;
        float pa0 = 0.f, pa1 = 0.f;
        float pc0[3] = {0.f, 0.f, 0.f}, pc1[3] = {0.f, 0.f, 0.f};
#pragma unroll
        for (int g = 0; g < 4; ++g) {
            int nb = nwarp * 64 + g * 16;
#pragma unroll
            for (int h = 0; h < 2; ++h) {
                int col = nb + h * 8 + (lane & 3) * 2;
                float* d = acc[mt][2 * g + h];
                float f0 = d[0] + bias[col], f1 = d[1] + bias[col + 1];
                float f2 = d[2] + bias[col], f3 = d[3] + bias[col + 1];
                if (MODE != 1) {
                    f0 = fmaxf(f0, 0.f); f1 = fmaxf(f1, 0.f);
                    f2 = fmaxf(f2, 0.f); f3 = fmaxf(f3, 0.f);
                }
                if (MODE <= 1) {
                    uint32_t h0, l0, h1, l1;
                    split2(f0, f1, h0, l0); split2(f2, f3, h1, l1);
                    *(uint32_t*)(AHI + r0 * ASTR + col) = h0;
                    *(uint32_t*)(ALO + r0 * ASTR + col) = l0;
                    *(uint32_t*)(AHI + r1 * ASTR + col) = h1;
                    *(uint32_t*)(ALO + r1 * ASTR + col) = l1;
                } else if (MODE == 2) {
                    float w0 = __ldg(g_aWd + col), w1 = __ldg(g_aWd + col + 1);
                    pa0 += f0 * w0 + f1 * w1;
                    pa1 += f2 * w0 + f3 * w1;
                } else {
#pragma unroll
                    for (int j = 0; j < 3; ++j) {
                        float w0 = __ldg(g_cWd + col * 3 + j), w1 = __ldg(g_cWd + (col + 1) * 3 + j);
                        pc0[j] += f0 * w0 + f1 * w1;
                        pc1[j] += f2 * w0 + f3 * w1;
                    }
                }
            }
        }
        if (MODE == 2) {
            pa0 += __shfl_xor_sync(~0u, pa0, 1); pa0 += __shfl_xor_sync(~0u, pa0, 2);
            pa1 += __shfl_xor_sync(~0u, pa1, 1); pa1 += __shfl_xor_sync(~0u, pa1, 2);
            if ((lane & 3) == 0) {
                atomicAdd(crow + r0 * 4 + 3, pa0);
                atomicAdd(crow + r1 * 4 + 3, pa1);
            }
        } else if (MODE == 3) {
#pragma unroll
            for (int j = 0; j < 3; ++j) {
                pc0[j] += __shfl_xor_sync(~0u, pc0[j], 1); pc0[j] += __shfl_xor_sync(~0u, pc0[j], 2);
                pc1[j] += __shfl_xor_sync(~0u, pc1[j], 1); pc1[j] += __shfl_xor_sync(~0u, pc1[j], 2);
            }
            if ((lane & 3) == 0) {
#pragma unroll
                for (int j = 0; j < 3; ++j) {
                    atomicAdd(crow + r0 * 4 + j, pc0[j]);
                    atomicAdd(crow + r1 * 4 + j, pc1[j]);
                }
            }
        }
    }
}

// ---------------- main kernel ----------------
__global__ void __launch_bounds__(NTHR, 1)
mesh_main(const int* __restrict__ verts, const float* __restrict__ barys,
          const float* __restrict__ views, const float* __restrict__ emb,
          const float* __restrict__ b_proj, const float* __restrict__ view_b,
          const float* __restrict__ vert_b, float* __restrict__ out)
{
    extern __shared__ char sm[];
    uint32_t smb = smem_u32(sm);
    const int tid = threadIdx.x, lane = tid & 31, w = tid >> 5;
    const int base = blockIdx.x * 128;

    __nv_bfloat16* AHI = (__nv_bfloat16*)(sm + OFF_AHI);
    __nv_bfloat16* ALO = (__nv_bfloat16*)(sm + OFF_ALO);
    float* sbias = (float*)(sm + OFF_BIAS);
    float* crow  = (float*)(sm + OFF_CROW);
    float* sscl  = (float*)(sm + OFF_SCL);

    // prefetch first weight chunk immediately (overlaps gather)
    copy_chunk32(smb + OFF_WBUF, g_wT[0][0], g_wT[0][1], 256, 0, tid);

    // stage constants
    for (int i = tid; i < 1280; i += NTHR) {
        float v;
        if (i < 512) v = vert_b[i];
        else if (i < 768) v = b_proj[i - 512];
        else v = view_b[i - 768];
        sbias[i] = v;
    }
    if (tid < 128) {
        crow[tid * 4 + 0] = g_cbd[0]; crow[tid * 4 + 1] = g_cbd[1];
        crow[tid * 4 + 2] = g_cbd[2]; crow[tid * 4 + 3] = g_abd;
    }

    // ---- gather phase A: per-(row,vertex) norms ----
    for (int task = w; task < 384; task += 16) {
        int rr = task / 3, v = task - rr * 3;
        int grow = base + rr;
        int idx = verts[grow * 3 + v] + 1;
        const float* ep = emb + ((size_t)(grow & 7) * NTAB + (size_t)idx) * NC + lane * 8;
        float4 e0 = *(const float4*)ep, e1 = *(const float4*)(ep + 4);
        float ss = e0.x*e0.x + e0.y*e0.y + e0.z*e0.z + e0.w*e0.w
                 + e1.x*e1.x + e1.y*e1.y + e1.z*e1.z + e1.w*e1.w;
#pragma unroll
        for (int o = 16; o > 0; o >>= 1) ss += __shfl_xor_sync(~0u, ss, o);
        float s = barys[grow * 3 + v];
        float nrm = sqrtf(ss);
        if (nrm > 1.f) s *= 1.f / fmaxf(nrm, 1e-7f);
        if (lane == 0) sscl[task] = s;
    }
    __syncthreads();

    // ---- gather phase B: blend -> split bf16 into A bufs, color partials ----
    for (int r = w; r < 128; r += 16) {
        int grow = base + r;
        float v[8];
#pragma unroll
        for (int j = 0; j < 8; ++j) v[j] = 0.f;
#pragma unroll
        for (int vt = 0; vt < 3; ++vt) {
            float s = sscl[r * 3 + vt];
            int idx = verts[grow * 3 + vt] + 1;
            const float* ep = emb + ((size_t)(grow & 7) * NTAB + (size_t)idx) * NC + lane * 8;
            float4 e0 = *(const float4*)ep, e1 = *(const float4*)(ep + 4);
            v[0] += s*e0.x; v[1] += s*e0.y; v[2] += s*e0.z; v[3] += s*e0.w;
            v[4] += s*e1.x; v[5] += s*e1.y; v[6] += s*e1.z; v[7] += s*e1.w;
        }
        int cbase = lane * 8;
#pragma unroll
        for (int p = 0; p < 4; ++p) {
            uint32_t h, l;
            split2(v[2 * p], v[2 * p + 1], h, l);
            *(uint32_t*)(AHI + r * ASTR + cbase + 2 * p) = h;
            *(uint32_t*)(ALO + r * ASTR + cbase + 2 * p) = l;
        }
        float p0 = 0.f, p1 = 0.f, p2 = 0.f;
#pragma unroll
        for (int j = 0; j < 8; ++j) {
            const float* w3 = g_cWd + (size_t)(256 + cbase + j) * 3;
            p0 += v[j] * __ldg(w3); p1 += v[j] * __ldg(w3 + 1); p2 += v[j] * __ldg(w3 + 2);
        }
#pragma unroll
        for (int o = 16; o > 0; o >>= 1) {
            p0 += __shfl_xor_sync(~0u, p0, o);
            p1 += __shfl_xor_sync(~0u, p1, o);
            p2 += __shfl_xor_sync(~0u, p2, o);
        }
        if (lane == 0) {
            crow[r * 4 + 0] += p0; crow[r * 4 + 1] += p1; crow[r * 4 + 2] += p2;
        }
    }

    // ---- vert branch ----
    do_layer<256, 0>(sm, smb, g_wT[0][0], g_wT[0][1], sbias,       g_wT[1][0], g_wT[1][1], 256);
    do_layer<256, 2>(sm, smb, g_wT[1][0], g_wT[1][1], sbias + 256, g_wP[0],    g_wP[1],    64);

    // ---- sincos -> A bufs (K padded to 64) ----
    if (tid < 128) {
        int row = base + tid;
        float x0 = views[row * 3], x1 = views[row * 3 + 1], x2 = views[row * 3 + 2];
        float em[36];
#pragma unroll
        for (int l = 0; l < 6; ++l) {
            float f = (float)(1 << l);
            em[l * 6 + 0] = sinf(f * x0); em[l * 6 + 1] = sinf(f * x1); em[l * 6 + 2] = sinf(f * x2);
            em[l * 6 + 3] = cosf(f * x0); em[l * 6 + 4] = cosf(f * x1); em[l * 6 + 5] = cosf(f * x2);
        }
#pragma unroll
        for (int p = 0; p < 18; ++p) {
            uint32_t h, l;
            split2(em[2 * p], em[2 * p + 1], h, l);
            *(uint32_t*)(AHI + tid * ASTR + 2 * p) = h;
            *(uint32_t*)(ALO + tid * ASTR + 2 * p) = l;
        }
#pragma unroll
        for (int p = 18; p < 32; ++p) {
            *(uint32_t*)(AHI + tid * ASTR + 2 * p) = 0u;
            *(uint32_t*)(ALO + tid * ASTR + 2 * p) = 0u;
        }
    }

    // ---- view branch ----
    do_layer<64, 1>(sm, smb, g_wP[0], g_wP[1], sbias + 512,          g_wT[2][0], g_wT[2][1], 256);
    do_layer<256, 0>(sm, smb, g_wT[2][0], g_wT[2][1], sbias + 768,   g_wT[3][0], g_wT[3][1], 256);
    do_layer<256, 3>(sm, smb, g_wT[3][0], g_wT[3][1], sbias + 1024,  (const __nv_bfloat16*)0, (const __nv_bfloat16*)0, 0);

    __syncthreads();
    if (tid < 128) {
        float4 ov = make_float4(crow[tid * 4 + 0], crow[tid * 4 + 1],
                                crow[tid * 4 + 2], crow[tid * 4 + 3]);
        *(float4*)(out + (size_t)(base + tid) * 4) = ov;
    }
}

extern "C" void kernel_launch(void* const* d_in, const int* in_sizes, int n_in,
                              void* d_out, int out_size)
{
    const int*   verts  = (const int*)  d_in[0];
    const float* barys  = (const float*)d_in[1];
    const float* views  = (const float*)d_in[2];
    const float* emb    = (const float*)d_in[3];
    const float* w_proj = (const float*)d_in[4];
    const float* b_proj = (const float*)d_in[5];
    const float* view_W = (const float*)d_in[6];
    const float* view_b = (const float*)d_in[7];
    const float* vert_W = (const float*)d_in[8];
    const float* vert_b = (const float*)d_in[9];
    const float* aW1    = (const float*)d_in[10];
    const float* ab1    = (const float*)d_in[11];
    const float* aW2    = (const float*)d_in[12];
    const float* ab2    = (const float*)d_in[13];
    const float* cW1    = (const float*)d_in[14];
    const float* cb1    = (const float*)d_in[15];
    const float* cW2    = (const float*)d_in[16];
    const float* cb2    = (const float*)d_in[17];
    float* out = (float*)d_out;

    prep_kernel<<<1096, 256>>>(w_proj, view_W, vert_W, aW1, ab1, aW2, ab2,
                               cW1, cb1, cW2, cb2);

    cudaFuncSetAttribute(mesh_main, cudaFuncAttributeMaxDynamicSharedMemorySize, SM_REQ);
    mesh_main<<<NROWS / 128, NTHR, SM_REQ>>>(verts, barys, views, emb,
                                             b_proj, view_b, vert_b, out);
}